// round 2
// baseline (speedup 1.0000x reference)
#include <cuda_runtime.h>
#include <cuda_bf16.h>

#define N_NODES 100000
#define N_EDGES 1600000
#define C 64
#define TILE 64
#define HPAD 68   // padded row stride (floats) for h/hn tiles

// ---------------- scratch (device globals: no allocations allowed) ----------------
__device__ __align__(16) float g_h0[N_NODES * C];
__device__ __align__(16) float g_h1[N_NODES * C];
__device__ __align__(16) float g_ideg[N_NODES];
__device__ int g_cnt[N_NODES];
__device__ int g_row_ptr[N_NODES + 1];
__device__ int g_cursor[N_NODES];
__device__ int g_csr_src[N_EDGES];

// ---------------- CSR build ----------------
__global__ void zero_cnt_kernel(int* __restrict__ cnt) {
    int i = blockIdx.x * blockDim.x + threadIdx.x;
    if (i < N_NODES) cnt[i] = 0;
}

__global__ void hist_kernel(const int* __restrict__ dst, int* __restrict__ cnt) {
    int e = blockIdx.x * blockDim.x + threadIdx.x;
    if (e < N_EDGES) atomicAdd(&cnt[dst[e]], 1);
}

// single-block exclusive scan of counts -> row_ptr, cursor, ideg
__global__ __launch_bounds__(1024) void scan_kernel(
    const int* __restrict__ cnt, int* __restrict__ row_ptr,
    int* __restrict__ cursor, float* __restrict__ ideg)
{
    __shared__ int part[1024];
    const int t = threadIdx.x;
    const int CH = (N_NODES + 1023) / 1024;   // 98
    int begin = t * CH;
    int end = begin + CH; if (end > N_NODES) end = N_NODES;
    int s = 0;
    for (int i = begin; i < end; i++) s += cnt[i];
    part[t] = s;
    __syncthreads();
    // Hillis-Steele inclusive scan
    for (int off = 1; off < 1024; off <<= 1) {
        int u = (t >= off) ? part[t - off] : 0;
        __syncthreads();
        part[t] += u;
        __syncthreads();
    }
    int run = part[t] - s;   // exclusive prefix of this thread's chunk
    for (int i = begin; i < end; i++) {
        int c = cnt[i];
        row_ptr[i] = run;
        cursor[i]  = run;
        ideg[i] = 1.0f / (float)(c > 1 ? c : 1);
        run += c;
    }
    if (t == 1023) row_ptr[N_NODES] = part[1023];
}

__global__ void fill_kernel(const int* __restrict__ src, const int* __restrict__ dst,
                            int* __restrict__ cursor, int* __restrict__ csr_src) {
    int e = blockIdx.x * blockDim.x + threadIdx.x;
    if (e < N_EDGES) {
        int pos = atomicAdd(&cursor[dst[e]], 1);
        csr_src[pos] = src[e];
    }
}

// ---------------- fused: gather-mean + dual GEMM + bias + rownorm [+ BN+ReLU] ----
// Block: 256 threads, tile of 64 nodes x 64 channels.
// Gather phase: each 16-thread group owns one node row (4 floats/thread),
// walks CSR neighbor list accumulating in registers (no atomics).
// GEMM phase: thread owns 4 nodes x 4 channels; W transposed in smem.
__global__ __launch_bounds__(256) void sage_fused_kernel(
    const float* __restrict__ h,
    const int* __restrict__ row_ptr, const int* __restrict__ csr_src,
    const float* __restrict__ ideg,
    const float* __restrict__ w1, const float* __restrict__ w2,
    const float* __restrict__ b2,
    const float* __restrict__ bn_g, const float* __restrict__ bn_b,
    const float* __restrict__ bn_m, const float* __restrict__ bn_v,
    float* __restrict__ out, int apply_bn)
{
    extern __shared__ float smem[];
    float* sh  = smem;                    // [64][HPAD]
    float* sn  = sh + TILE * HPAD;        // [64][HPAD]
    float* sw1 = sn + TILE * HPAD;        // [64][64] transposed: sw1[k*64+c]
    float* sw2 = sw1 + 64 * 64;           // [64][64]
    float* sb  = sw2 + 64 * 64;           // [64]
    float* ssc = sb + 64;                 // [64] bn scale
    float* sbs = ssc + 64;                // [64] bn bias

    const int t = threadIdx.x;
    const int node0 = blockIdx.x * TILE;

    // load weights transposed (w global layout [c][k])
    #pragma unroll
    for (int i = t; i < 64 * 64; i += 256) {
        int c = i >> 6, k = i & 63;
        sw1[k * 64 + c] = w1[i];
        sw2[k * 64 + c] = w2[i];
    }
    if (t < 64) {
        sb[t] = b2[t];
        if (apply_bn) {
            float sc = bn_g[t] * rsqrtf(bn_v[t] + 1e-5f);
            ssc[t] = sc;
            sbs[t] = bn_b[t] - bn_m[t] * sc;
        }
    }

    const int grp = t >> 4;          // 0..15: node group
    const int c4  = (t & 15) << 2;   // float4 channel base

    // own-node h tile (coalesced; 16 threads per row)
    #pragma unroll
    for (int it = 0; it < 4; it++) {
        int row = it * 16 + grp;
        int node = node0 + row;
        float4 hv = make_float4(0.f, 0.f, 0.f, 0.f);
        if (node < N_NODES) hv = *(const float4*)(h + node * C + c4);
        *(float4*)(sh + row * HPAD + c4) = hv;
    }

    // CSR gather-mean into sn
    #pragma unroll
    for (int it = 0; it < 4; it++) {
        int row = it * 16 + grp;
        int node = node0 + row;
        float4 a = make_float4(0.f, 0.f, 0.f, 0.f);
        if (node < N_NODES) {
            int beg = __ldg(&row_ptr[node]);
            int end = __ldg(&row_ptr[node + 1]);
            int j = beg;
            // 2-way unrolled for MLP
            for (; j + 1 < end; j += 2) {
                int s0 = __ldg(&csr_src[j]);
                int s1 = __ldg(&csr_src[j + 1]);
                float4 v0 = *(const float4*)(h + s0 * C + c4);
                float4 v1 = *(const float4*)(h + s1 * C + c4);
                a.x += v0.x + v1.x;
                a.y += v0.y + v1.y;
                a.z += v0.z + v1.z;
                a.w += v0.w + v1.w;
            }
            if (j < end) {
                int s0 = __ldg(&csr_src[j]);
                float4 v0 = *(const float4*)(h + s0 * C + c4);
                a.x += v0.x; a.y += v0.y; a.z += v0.z; a.w += v0.w;
            }
            float id = ideg[node];
            a.x *= id; a.y *= id; a.z *= id; a.w *= id;
        }
        *(float4*)(sn + row * HPAD + c4) = a;
    }
    __syncthreads();

    const int cg = (t & 15) << 2;   // channel base
    const int ng = (t >> 4) << 2;   // node base within tile

    float acc[4][4];
    #pragma unroll
    for (int i = 0; i < 4; i++)
        #pragma unroll
        for (int j = 0; j < 4; j++) acc[i][j] = 0.f;

    #pragma unroll 8
    for (int k = 0; k < 64; k++) {
        float4 w1v = *(const float4*)(sw1 + k * 64 + cg);
        float4 w2v = *(const float4*)(sw2 + k * 64 + cg);
        #pragma unroll
        for (int i = 0; i < 4; i++) {
            float a = sh[(ng + i) * HPAD + k];
            float b = sn[(ng + i) * HPAD + k];
            acc[i][0] = fmaf(a, w1v.x, fmaf(b, w2v.x, acc[i][0]));
            acc[i][1] = fmaf(a, w1v.y, fmaf(b, w2v.y, acc[i][1]));
            acc[i][2] = fmaf(a, w1v.z, fmaf(b, w2v.z, acc[i][2]));
            acc[i][3] = fmaf(a, w1v.w, fmaf(b, w2v.w, acc[i][3]));
        }
    }

    // epilogue: +bias, row L2-norm (16-thread shuffle reduce), BN+ReLU, store
    float ss[4];
    #pragma unroll
    for (int i = 0; i < 4; i++) {
        float s = 0.f;
        #pragma unroll
        for (int j = 0; j < 4; j++) {
            float v = acc[i][j] + sb[cg + j];
            acc[i][j] = v;
            s = fmaf(v, v, s);
        }
        ss[i] = s;
    }
    #pragma unroll
    for (int m = 1; m < 16; m <<= 1)
        #pragma unroll
        for (int i = 0; i < 4; i++)
            ss[i] += __shfl_xor_sync(0xffffffffu, ss[i], m);

    #pragma unroll
    for (int i = 0; i < 4; i++) {
        int node = node0 + ng + i;
        if (node >= N_NODES) continue;
        float nrm = sqrtf(ss[i]);
        float scale = 1.0f / fmaxf(nrm, 1e-12f);
        float v0 = acc[i][0] * scale;
        float v1 = acc[i][1] * scale;
        float v2 = acc[i][2] * scale;
        float v3 = acc[i][3] * scale;
        if (apply_bn) {
            v0 = fmaxf(fmaf(v0, ssc[cg + 0], sbs[cg + 0]), 0.f);
            v1 = fmaxf(fmaf(v1, ssc[cg + 1], sbs[cg + 1]), 0.f);
            v2 = fmaxf(fmaf(v2, ssc[cg + 2], sbs[cg + 2]), 0.f);
            v3 = fmaxf(fmaf(v3, ssc[cg + 3], sbs[cg + 3]), 0.f);
        }
        float4 o = make_float4(v0, v1, v2, v3);
        *(float4*)(out + node * C + cg) = o;
    }
}

// ---------------- host ----------------
static const int SMEM_BYTES = (2 * TILE * HPAD + 2 * 64 * 64 + 3 * 64) * 4;

extern "C" void kernel_launch(void* const* d_in, const int* in_sizes, int n_in,
                              void* d_out, int out_size) {
    const float* x    = (const float*)d_in[0];
    const int*   esrc = (const int*)d_in[1];
    const int*   edst = (const int*)d_in[2];

    // Input-order sniffing: dict order has w1_1 (4096) at index 6,
    // signature order has bn_g_0 (64) there.
    int iw1[3], iw2[3], ib2[3], ibn[2][4];
    if (n_in > 6 && in_sizes[6] == 4096) {
        for (int l = 0; l < 3; l++) { iw1[l] = 3 + 3 * l; iw2[l] = 4 + 3 * l; ib2[l] = 5 + 3 * l; }
        for (int l = 0; l < 2; l++)
            for (int j = 0; j < 4; j++) ibn[l][j] = 12 + 4 * l + j;
    } else {
        iw1[0] = 3;  iw2[0] = 4;  ib2[0] = 5;
        for (int j = 0; j < 4; j++) ibn[0][j] = 6 + j;
        iw1[1] = 10; iw2[1] = 11; ib2[1] = 12;
        for (int j = 0; j < 4; j++) ibn[1][j] = 13 + j;
        iw1[2] = 17; iw2[2] = 18; ib2[2] = 19;
    }

    float *h0, *h1, *ideg;
    int *cnt, *row_ptr, *cursor, *csr_src;
    cudaGetSymbolAddress((void**)&h0,     g_h0);
    cudaGetSymbolAddress((void**)&h1,     g_h1);
    cudaGetSymbolAddress((void**)&ideg,   g_ideg);
    cudaGetSymbolAddress((void**)&cnt,    g_cnt);
    cudaGetSymbolAddress((void**)&row_ptr, g_row_ptr);
    cudaGetSymbolAddress((void**)&cursor, g_cursor);
    cudaGetSymbolAddress((void**)&csr_src, g_csr_src);

    cudaFuncSetAttribute(sage_fused_kernel,
                         cudaFuncAttributeMaxDynamicSharedMemorySize, SMEM_BYTES);

    const int NB_NODE  = (N_NODES + 255) / 256;
    const int NB_EDGE  = (N_EDGES + 255) / 256;
    const int NB_GEMM  = (N_NODES + TILE - 1) / TILE;

    // ---- CSR build (once per launch; graph is static across layers) ----
    zero_cnt_kernel<<<NB_NODE, 256>>>(cnt);
    hist_kernel<<<NB_EDGE, 256>>>(edst, cnt);
    scan_kernel<<<1, 1024>>>(cnt, row_ptr, cursor, ideg);
    fill_kernel<<<NB_EDGE, 256>>>(esrc, edst, cursor, csr_src);

    const float* hin = x;
    float* houts[3] = {h0, h1, (float*)d_out};

    for (int l = 0; l < 3; l++) {
        int has_bn = (l < 2);
        sage_fused_kernel<<<NB_GEMM, 256, SMEM_BYTES>>>(
            hin, row_ptr, csr_src, ideg,
            (const float*)d_in[iw1[l]], (const float*)d_in[iw2[l]],
            (const float*)d_in[ib2[l]],
            has_bn ? (const float*)d_in[ibn[l][0]] : (const float*)d_in[ib2[l]],
            has_bn ? (const float*)d_in[ibn[l][1]] : (const float*)d_in[ib2[l]],
            has_bn ? (const float*)d_in[ibn[l][2]] : (const float*)d_in[ib2[l]],
            has_bn ? (const float*)d_in[ibn[l][3]] : (const float*)d_in[ib2[l]],
            houts[l], has_bn);
        hin = houts[l];
    }
}